// round 3
// baseline (speedup 1.0000x reference)
#include <cuda_runtime.h>
#include <math.h>

#define BN 64
#define SN 512
#define DN 768
#define HN 384
#define GN 1536
#define TN 22

#define NBLK_REC 128
#define REC_THREADS 384

// ---------------- scratch (static device globals; no runtime allocation) ----
__device__ float g_embeds[BN * SN * DN];                 // aligned embeds
__device__ float g_xg[2 * SN * BN * GN];                 // [dir][t][b][4H] input projections
__device__ float g_lstm[BN * SN * 2 * HN];               // [b][t][2H] lstm outputs
__device__ float g_h[2 * 2 * BN * HN];                   // [dir][parity][b][H]
__device__ int   g_n[BN];
__device__ int   g_sent[BN];
__device__ int   g_last[BN];
__device__ unsigned g_bar_count = 0;
__device__ unsigned g_bar_gen = 0;

// ---------------- helpers ---------------------------------------------------
__device__ __forceinline__ long long ld_idx(const void* p, int i, bool is64) {
    return is64 ? ((const long long*)p)[i] : (long long)((const int*)p)[i];
}

__device__ __forceinline__ bool detect_is64(const void* start_ids) {
    // start_ids[b=0,t=0] == 1 always (nw >= 1). int64 -> words {1,0}; int32 -> {1, next_sid!=0}
    return ((const int*)start_ids)[1] == 0;
}

// Software grid barrier: all NBLK_REC blocks are co-resident (128 blocks, 1/SM, 148 SMs).
__device__ __forceinline__ void grid_barrier() {
    __syncthreads();
    if (threadIdx.x == 0) {
        __threadfence();
        volatile unsigned* genp = &g_bar_gen;
        unsigned gen = *genp;
        unsigned ticket = atomicAdd(&g_bar_count, 1u);
        if (ticket == NBLK_REC - 1) {
            g_bar_count = 0;
            __threadfence();
            *genp = gen + 1;
        } else {
            while (*genp == gen) { __nanosleep(64); }
        }
        __threadfence();
    }
    __syncthreads();
}

// ---------------- K0: per-batch metadata ------------------------------------
__global__ void meta_kernel(const void* start_ids, const void* masks) {
    int b = blockIdx.x;
    int tid = threadIdx.x;
    bool is64 = detect_is64(start_ids);
    __shared__ int red[256];
    int cnt = 0, sm = 0;
    for (int t = tid; t < SN; t += 256) {
        long long sv = ld_idx(start_ids, b * SN + t, is64);
        long long mv = ld_idx(masks, b * SN + t, is64);
        cnt += (sv >= 0);
        sm += (int)mv;
    }
    red[tid] = cnt; __syncthreads();
    for (int o = 128; o > 0; o >>= 1) { if (tid < o) red[tid] += red[tid + o]; __syncthreads(); }
    int ntot = red[0]; __syncthreads();
    red[tid] = sm; __syncthreads();
    for (int o = 128; o > 0; o >>= 1) { if (tid < o) red[tid] += red[tid + o]; __syncthreads(); }
    int stot = red[0];
    if (tid == 0) {
        g_n[b] = ntot;
        g_sent[b] = stot;
        long long last = 0;
        if (ntot > 0) last = ld_idx(start_ids, b * SN + ntot - 1, is64);
        g_last[b] = (int)last;
    }
}

// ---------------- K1: align gather -------------------------------------------
__global__ void gather_kernel(const float* __restrict__ hs, const void* __restrict__ start_ids) {
    int t = blockIdx.x, b = blockIdx.y;
    int sent = g_sent[b];
    if (t >= sent) return;   // rows t >= sent are never read downstream
    bool is64 = detect_is64(start_ids);
    int n = g_n[b];
    long long idx;
    if (t == 0)      idx = 0;
    else if (t < n)  idx = ld_idx(start_ids, b * SN + t, is64) - 1;
    else if (t == n) idx = g_last[b];
    else             idx = 0;
    if (idx < 0) idx = 0;
    if (idx > SN - 1) idx = SN - 1;
    const float4* src = (const float4*)(hs + ((size_t)b * SN + (size_t)idx) * DN);
    float4* dst = (float4*)(g_embeds + ((size_t)b * SN + t) * DN);
    dst[threadIdx.x] = src[threadIdx.x];
}

// ---------------- K2: input projection GEMM (fp32, 64x64 tiles) --------------
// xg[dir][t][b][n] = sum_k embeds[b,t,k] * Wih[n,k] + bih[n] + bhh[n], only for t < sent[b]
__global__ void __launch_bounds__(256) proj_kernel(
    const float* __restrict__ Wf, const float* __restrict__ Wb,
    const float* __restrict__ bihf, const float* __restrict__ bhhf,
    const float* __restrict__ bihb, const float* __restrict__ bhhb)
{
    int b = blockIdx.z & 63;
    int dir = blockIdx.z >> 6;
    int sent = g_sent[b];
    int t0 = blockIdx.y * 64;
    if (t0 >= sent) return;
    int n0 = blockIdx.x * 64;

    const float* W   = dir ? Wb   : Wf;
    const float* bih = dir ? bihb : bihf;
    const float* bhh = dir ? bhhb : bhhf;

    __shared__ float As[16][68];
    __shared__ float Bs[16][68];

    int tid = threadIdx.x;
    int lm = tid >> 2;            // 0..63 row within tile
    int lk = (tid & 3) * 4;       // 0,4,8,12
    int tx = tid & 15, ty = tid >> 4;

    float acc[4][4] = {};
    const float* Abase = g_embeds + ((size_t)b * SN + t0) * DN;
    const float* Bbase = W + (size_t)(n0 + lm) * DN;

    for (int kt = 0; kt < DN; kt += 16) {
        float4 av = *(const float4*)(Abase + (size_t)lm * DN + kt + lk);
        float4 bv = *(const float4*)(Bbase + kt + lk);
        As[lk + 0][lm] = av.x; As[lk + 1][lm] = av.y; As[lk + 2][lm] = av.z; As[lk + 3][lm] = av.w;
        Bs[lk + 0][lm] = bv.x; Bs[lk + 1][lm] = bv.y; Bs[lk + 2][lm] = bv.z; Bs[lk + 3][lm] = bv.w;
        __syncthreads();
        #pragma unroll
        for (int k = 0; k < 16; k++) {
            float4 a4 = *(const float4*)&As[k][ty * 4];
            float4 b4 = *(const float4*)&Bs[k][tx * 4];
            acc[0][0] += a4.x * b4.x; acc[0][1] += a4.x * b4.y; acc[0][2] += a4.x * b4.z; acc[0][3] += a4.x * b4.w;
            acc[1][0] += a4.y * b4.x; acc[1][1] += a4.y * b4.y; acc[1][2] += a4.y * b4.z; acc[1][3] += a4.y * b4.w;
            acc[2][0] += a4.z * b4.x; acc[2][1] += a4.z * b4.y; acc[2][2] += a4.z * b4.z; acc[2][3] += a4.z * b4.w;
            acc[3][0] += a4.w * b4.x; acc[3][1] += a4.w * b4.y; acc[3][2] += a4.w * b4.z; acc[3][3] += a4.w * b4.w;
        }
        __syncthreads();
    }

    float bs0 = bih[n0 + tx * 4 + 0] + bhh[n0 + tx * 4 + 0];
    float bs1 = bih[n0 + tx * 4 + 1] + bhh[n0 + tx * 4 + 1];
    float bs2 = bih[n0 + tx * 4 + 2] + bhh[n0 + tx * 4 + 2];
    float bs3 = bih[n0 + tx * 4 + 3] + bhh[n0 + tx * 4 + 3];

    #pragma unroll
    for (int mm = 0; mm < 4; mm++) {
        int t = t0 + ty * 4 + mm;
        if (t < sent) {
            float4 v;
            v.x = acc[mm][0] + bs0; v.y = acc[mm][1] + bs1;
            v.z = acc[mm][2] + bs2; v.w = acc[mm][3] + bs3;
            *(float4*)&g_xg[((size_t)(dir * SN + t) * BN + b) * GN + n0 + tx * 4] = v;
        }
    }
}

// ---------------- K3: persistent bidirectional LSTM recurrence ---------------
// 128 blocks: blk>>6 = dir, (blk&63)*6 = hidden slice offset j0 (6 units x 4 gates each).
__global__ void __launch_bounds__(REC_THREADS) lstm_kernel(
    const float* __restrict__ Whhf, const float* __restrict__ Whhb,
    const float* __restrict__ bihf, const float* __restrict__ bhhf,
    const float* __restrict__ bihb, const float* __restrict__ bhhb,
    const float* __restrict__ h0, const float* __restrict__ c0)
{
    extern __shared__ float sm_[];
    float* ws     = sm_;                        // 24*384 = 9216  : Whh slice
    float* hs     = sm_ + 9216;                 // 64*388 = 24832 : staged h (padded)
    float* gs     = sm_ + 9216 + 24832;         // 64*25  = 1600  : gate workspace
    float* bias_s = gs + 1600;                  // 24
    int*   sent_s = (int*)(bias_s + 24);        // 64

    int tid = threadIdx.x;
    int blk = blockIdx.x;
    int dir = blk >> 6;
    int j0 = (blk & 63) * 6;

    const float* Whh = dir ? Whhb : Whhf;
    const float* bih = dir ? bihb : bihf;
    const float* bhh = dir ? bhhb : bhhf;

    // load persistent Whh slice (rows gate*H + j0 + j, r = gate*6+j)
    for (int idx = tid; idx < 24 * HN; idx += REC_THREADS) {
        int r = idx / HN, k = idx % HN;
        int wrow = (r / 6) * HN + j0 + (r % 6);
        ws[r * HN + k] = Whh[(size_t)wrow * HN + k];
    }
    if (tid < 24) {
        int ng = (tid / 6) * HN + j0 + (tid % 6);
        bias_s[tid] = bih[ng] + bhh[ng];
    }
    if (tid < BN) sent_s[tid] = g_sent[tid];

    int be = tid / 6, je = tid % 6;             // elementwise ownership (b, j)
    // init h parity-0 buffer (this block's slice) and carried c in a register
    g_h[((dir * 2 + 0) * BN + be) * HN + j0 + je] = h0[((size_t)dir * BN + be) * HN + j0 + je];
    float creg = c0[((size_t)dir * BN + be) * HN + j0 + je];

    int q = tid >> 6;                           // 0..5 (uniform per warp)
    int bb = tid & 63;

    grid_barrier();

    for (int s = 0; s < SN; s++) {
        int p = s & 1;
        int t = dir ? (SN - 1 - s) : s;

        // stage full previous h into smem (coalesced float4)
        const float* hsrc = g_h + ((dir * 2 + p) * BN) * HN;
        for (int idx = tid; idx < BN * 96; idx += REC_THREADS) {
            int b2 = idx / 96, k4 = (idx % 96) * 4;
            *(float4*)&hs[b2 * 388 + k4] = *(const float4*)&hsrc[b2 * HN + k4];
        }
        // preload gate workspace with xg (t < sent) or constant bias
        for (int idx = tid; idx < 1536; idx += REC_THREADS) {
            int b2 = idx / 24, r = idx % 24;
            float v;
            if (t < sent_s[b2])
                v = g_xg[(((size_t)dir * SN + t) * BN + b2) * GN + (r / 6) * HN + j0 + (r % 6)];
            else
                v = bias_s[r];
            gs[b2 * 25 + r] = v;
        }
        __syncthreads();

        // GEMV: each thread adds 4 gate rows (r = q*4..q*4+3) for batch bb
        {
            int r0 = q * 4;
            float a0 = gs[bb * 25 + r0 + 0];
            float a1 = gs[bb * 25 + r0 + 1];
            float a2 = gs[bb * 25 + r0 + 2];
            float a3 = gs[bb * 25 + r0 + 3];
            const float* hrow = &hs[bb * 388];
            const float* w0 = &ws[(r0 + 0) * HN];
            const float* w1 = &ws[(r0 + 1) * HN];
            const float* w2 = &ws[(r0 + 2) * HN];
            const float* w3 = &ws[(r0 + 3) * HN];
            #pragma unroll 4
            for (int k = 0; k < HN; k += 4) {
                float4 hv = *(const float4*)&hrow[k];
                float4 v0 = *(const float4*)&w0[k];
                float4 v1 = *(const float4*)&w1[k];
                float4 v2 = *(const float4*)&w2[k];
                float4 v3 = *(const float4*)&w3[k];
                a0 += hv.x * v0.x + hv.y * v0.y + hv.z * v0.z + hv.w * v0.w;
                a1 += hv.x * v1.x + hv.y * v1.y + hv.z * v1.z + hv.w * v1.w;
                a2 += hv.x * v2.x + hv.y * v2.y + hv.z * v2.z + hv.w * v2.w;
                a3 += hv.x * v3.x + hv.y * v3.y + hv.z * v3.z + hv.w * v3.w;
            }
            gs[bb * 25 + r0 + 0] = a0;
            gs[bb * 25 + r0 + 1] = a1;
            gs[bb * 25 + r0 + 2] = a2;
            gs[bb * 25 + r0 + 3] = a3;
        }
        __syncthreads();

        // elementwise LSTM cell update for (be, je)
        {
            float xi = gs[be * 25 + 0  + je];
            float xf = gs[be * 25 + 6  + je];
            float xc = gs[be * 25 + 12 + je];
            float xo = gs[be * 25 + 18 + je];
            float ig = 1.f / (1.f + expf(-xi));
            float fg = 1.f / (1.f + expf(-xf));
            float cg = tanhf(xc);
            float og = 1.f / (1.f + expf(-xo));
            creg = fg * creg + ig * cg;
            float hv = og * tanhf(creg);
            g_h[((dir * 2 + (p ^ 1)) * BN + be) * HN + j0 + je] = hv;
            g_lstm[((size_t)be * SN + t) * (2 * HN) + dir * HN + j0 + je] = hv;
        }
        grid_barrier();
    }
}

// ---------------- K4: output linear ------------------------------------------
__global__ void out_kernel(const float* __restrict__ Wlin, const float* __restrict__ blin,
                           float* __restrict__ out)
{
    int row = blockIdx.x;  // b*S + t
    __shared__ float rs[768];
    int tid = threadIdx.x;
    const float4* src = (const float4*)(g_lstm + (size_t)row * 768);
    if (tid < 192) ((float4*)rs)[tid] = src[tid];
    __syncthreads();
    int w = tid >> 5, l = tid & 31;
    for (int o = w; o < TN; o += 8) {
        float s = 0.f;
        const float* wr = Wlin + (size_t)o * 768;
        for (int k = l; k < 768; k += 32) s += rs[k] * wr[k];
        #pragma unroll
        for (int off = 16; off; off >>= 1) s += __shfl_down_sync(0xffffffffu, s, off);
        if (l == 0) out[(size_t)row * TN + o] = s + blin[o];
    }
}

// ---------------- launch ------------------------------------------------------
extern "C" void kernel_launch(void* const* d_in, const int* in_sizes, int n_in,
                              void* d_out, int out_size) {
    const float* hs   = (const float*)d_in[0];
    const float* h0   = (const float*)d_in[1];
    const float* c0   = (const float*)d_in[2];
    const float* Wihf = (const float*)d_in[3];
    const float* Whhf = (const float*)d_in[4];
    const float* bihf = (const float*)d_in[5];
    const float* bhhf = (const float*)d_in[6];
    const float* Wihb = (const float*)d_in[7];
    const float* Whhb = (const float*)d_in[8];
    const float* bihb = (const float*)d_in[9];
    const float* bhhb = (const float*)d_in[10];
    const float* Wlin = (const float*)d_in[11];
    const float* blin = (const float*)d_in[12];
    const void*  sid  = d_in[13];
    const void*  msk  = d_in[14];

    meta_kernel<<<BN, 256>>>(sid, msk);
    gather_kernel<<<dim3(SN, BN), 192>>>(hs, sid);
    proj_kernel<<<dim3(GN / 64, SN / 64, 2 * BN), 256>>>(Wihf, Wihb, bihf, bhhf, bihb, bhhb);

    const int rec_smem = (9216 + 24832 + 1600 + 24 + 64) * 4;
    cudaFuncSetAttribute(lstm_kernel, cudaFuncAttributeMaxDynamicSharedMemorySize, rec_smem);
    lstm_kernel<<<NBLK_REC, REC_THREADS, rec_smem>>>(Whhf, Whhb, bihf, bhhf, bihb, bhhb, h0, c0);

    out_kernel<<<BN * SN, 256>>>(Wlin, blin, (float*)d_out);
}

// round 4
// speedup vs baseline: 1.3293x; 1.3293x over previous
#include <cuda_runtime.h>
#include <math.h>

#define BN 64
#define SN 512
#define DN 768
#define HN 384
#define GN 1536
#define TN 22

#define NBLK_REC 128
#define REC_THREADS 384

// ---------------- scratch (static device globals; zero-initialized) ---------
__device__ float g_embeds[BN * SN * DN];                 // aligned embeds (rows >= sent stay 0)
__device__ float g_xg[2 * SN * BN * GN];                 // [dir][t][b][4H]
__device__ float g_lstm[BN * SN * 2 * HN];               // [b][t][2H]
__device__ float g_h[2 * 2 * BN * HN];                   // [dir][parity][b][H]
__device__ int   g_n[BN];
__device__ int   g_sent[BN];
__device__ int   g_last[BN];
__device__ unsigned g_bar_count = 0;
__device__ unsigned g_bar_gen = 0;

// ---------------- packed fp32x2 helpers --------------------------------------
__device__ __forceinline__ unsigned long long fma2(unsigned long long a,
                                                   unsigned long long b,
                                                   unsigned long long c) {
    unsigned long long d;
    asm("fma.rn.f32x2 %0, %1, %2, %3;" : "=l"(d) : "l"(a), "l"(b), "l"(c));
    return d;
}
__device__ __forceinline__ float unpack_sum(unsigned long long v) {
    float lo, hi;
    asm("mov.b64 {%0, %1}, %2;" : "=f"(lo), "=f"(hi) : "l"(v));
    return lo + hi;
}

// ---------------- index helpers ----------------------------------------------
__device__ __forceinline__ long long ld_idx(const void* p, int i, bool is64) {
    return is64 ? ((const long long*)p)[i] : (long long)((const int*)p)[i];
}
__device__ __forceinline__ bool detect_is64(const void* start_ids) {
    return ((const int*)start_ids)[1] == 0;
}

// Software grid barrier (128 blocks, 1/SM on 148 SMs -> all co-resident)
__device__ __forceinline__ void grid_barrier() {
    __syncthreads();
    if (threadIdx.x == 0) {
        __threadfence();
        volatile unsigned* genp = &g_bar_gen;
        unsigned gen = *genp;
        unsigned ticket = atomicAdd(&g_bar_count, 1u);
        if (ticket == NBLK_REC - 1) {
            g_bar_count = 0;
            __threadfence();
            *genp = gen + 1;
        } else {
            while (*genp == gen) { __nanosleep(64); }
        }
        __threadfence();
    }
    __syncthreads();
}

// ---------------- K0: per-batch metadata --------------------------------------
__global__ void meta_kernel(const void* start_ids, const void* masks) {
    int b = blockIdx.x;
    int tid = threadIdx.x;
    bool is64 = detect_is64(start_ids);
    __shared__ int red[256];
    int cnt = 0, sm = 0;
    for (int t = tid; t < SN; t += 256) {
        long long sv = ld_idx(start_ids, b * SN + t, is64);
        long long mv = ld_idx(masks, b * SN + t, is64);
        cnt += (sv >= 0);
        sm += (int)mv;
    }
    red[tid] = cnt; __syncthreads();
    for (int o = 128; o > 0; o >>= 1) { if (tid < o) red[tid] += red[tid + o]; __syncthreads(); }
    int ntot = red[0]; __syncthreads();
    red[tid] = sm; __syncthreads();
    for (int o = 128; o > 0; o >>= 1) { if (tid < o) red[tid] += red[tid + o]; __syncthreads(); }
    int stot = red[0];
    if (tid == 0) {
        g_n[b] = ntot;
        g_sent[b] = stot;
        long long last = 0;
        if (ntot > 0) last = ld_idx(start_ids, b * SN + ntot - 1, is64);
        g_last[b] = (int)last;
    }
}

// ---------------- K1: align gather ---------------------------------------------
__global__ void gather_kernel(const float* __restrict__ hs, const void* __restrict__ start_ids) {
    int t = blockIdx.x, b = blockIdx.y;
    int sent = g_sent[b];
    if (t >= sent) return;
    bool is64 = detect_is64(start_ids);
    int n = g_n[b];
    long long idx;
    if (t == 0)      idx = 0;
    else if (t < n)  idx = ld_idx(start_ids, b * SN + t, is64) - 1;
    else if (t == n) idx = g_last[b];
    else             idx = 0;
    if (idx < 0) idx = 0;
    if (idx > SN - 1) idx = SN - 1;
    const float4* src = (const float4*)(hs + ((size_t)b * SN + (size_t)idx) * DN);
    float4* dst = (float4*)(g_embeds + ((size_t)b * SN + t) * DN);
    dst[threadIdx.x] = src[threadIdx.x];
}

// ---------------- K2: input projection GEMM (f32x2, cp.async pipelined) --------
// 128x128 tile, 8x8 micro-tile, [m][k]-major smem (k-pairs packed for f32x2).
__global__ void __launch_bounds__(256, 1) proj_kernel(
    const float* __restrict__ Wf, const float* __restrict__ Wb,
    const float* __restrict__ bihf, const float* __restrict__ bhhf,
    const float* __restrict__ bihb, const float* __restrict__ bhhb)
{
    int b = blockIdx.z & 63;
    int dir = blockIdx.z >> 6;
    int sent = g_sent[b];
    int t0 = blockIdx.y * 128;
    if (t0 >= sent) return;
    int n0 = blockIdx.x * 128;

    const float* W   = dir ? Wb   : Wf;
    const float* bih = dir ? bihb : bihf;
    const float* bhh = dir ? bhhb : bhhf;

    __shared__ float As[2][128][20];
    __shared__ float Bs[2][128][20];

    int tid = threadIdx.x;
    int tx = tid & 15, ty = tid >> 4;

    unsigned long long acc[8][8];
    #pragma unroll
    for (int i = 0; i < 8; i++)
        #pragma unroll
        for (int j = 0; j < 8; j++) acc[i][j] = 0ull;

    // fill helper (2 x 16B per array per thread)
    #define PROJ_FILL(stg, kt)                                                          \
        do {                                                                            \
            _Pragma("unroll")                                                           \
            for (int f = 0; f < 2; f++) {                                               \
                int lin = tid + f * 256;                                                \
                int row = lin >> 2;                                                     \
                int c = (lin & 3) * 4;                                                  \
                unsigned sa = (unsigned)__cvta_generic_to_shared(&As[stg][row][c]);     \
                const float* ga = &g_embeds[((size_t)b * SN + t0 + row) * DN + (kt) + c]; \
                asm volatile("cp.async.ca.shared.global [%0], [%1], 16;" :: "r"(sa), "l"(ga)); \
                unsigned sb = (unsigned)__cvta_generic_to_shared(&Bs[stg][row][c]);     \
                const float* gb = &W[(size_t)(n0 + row) * DN + (kt) + c];               \
                asm volatile("cp.async.ca.shared.global [%0], [%1], 16;" :: "r"(sb), "l"(gb)); \
            }                                                                           \
            asm volatile("cp.async.commit_group;");                                     \
        } while (0)

    PROJ_FILL(0, 0);
    int st = 0;
    for (int kt = 0; kt < DN; kt += 16) {
        if (kt + 16 < DN) {
            PROJ_FILL(st ^ 1, kt + 16);
            asm volatile("cp.async.wait_group 1;");
        } else {
            asm volatile("cp.async.wait_group 0;");
        }
        __syncthreads();

        #pragma unroll
        for (int k = 0; k < 16; k += 4) {
            unsigned long long a0[8], a1[8], b0[8], b1[8];
            #pragma unroll
            for (int i = 0; i < 8; i++) {
                ulonglong2 v = *(const ulonglong2*)&As[st][ty + i * 16][k];
                a0[i] = v.x; a1[i] = v.y;
            }
            #pragma unroll
            for (int j = 0; j < 8; j++) {
                ulonglong2 v = *(const ulonglong2*)&Bs[st][tx + j * 16][k];
                b0[j] = v.x; b1[j] = v.y;
            }
            #pragma unroll
            for (int i = 0; i < 8; i++)
                #pragma unroll
                for (int j = 0; j < 8; j++) {
                    acc[i][j] = fma2(a0[i], b0[j], acc[i][j]);
                    acc[i][j] = fma2(a1[i], b1[j], acc[i][j]);
                }
        }
        __syncthreads();
        st ^= 1;
    }
    #undef PROJ_FILL

    float bsj[8];
    #pragma unroll
    for (int j = 0; j < 8; j++) {
        int n = n0 + tx + j * 16;
        bsj[j] = bih[n] + bhh[n];
    }
    #pragma unroll
    for (int i = 0; i < 8; i++) {
        int t = t0 + ty + i * 16;
        if (t < sent) {
            float* dst = &g_xg[((size_t)(dir * SN + t) * BN + b) * GN + n0 + tx];
            #pragma unroll
            for (int j = 0; j < 8; j++)
                dst[j * 16] = unpack_sum(acc[i][j]) + bsj[j];
        }
    }
}

// ---------------- K3: persistent bidirectional LSTM recurrence (f32x2) --------
// 128 blocks: dir = blk>>6, j0 = (blk&63)*6 (6 hidden units x 4 gates = 24 rows).
// Threads 384: ks=tid/96 (k-split 4), rg=(tid%96)/32 (row group of 8), bp=tid%32.
__global__ void __launch_bounds__(REC_THREADS) lstm_kernel(
    const float* __restrict__ Whhf, const float* __restrict__ Whhb,
    const float* __restrict__ bihf, const float* __restrict__ bhhf,
    const float* __restrict__ bihb, const float* __restrict__ bhhb,
    const float* __restrict__ h0, const float* __restrict__ c0)
{
    extern __shared__ float sm_[];
    float* ws     = sm_;                        // 24*384 = 9216
    float* hs     = sm_ + 9216;                 // 64*388 = 24832 (stride 388: 388%32==4)
    float* P      = sm_ + 9216 + 24832;         // 4*24*65 = 6240 partials
    float* bias_s = P + 6240;                   // 24
    int*   sent_s = (int*)(bias_s + 24);        // 64

    int tid = threadIdx.x;
    int blk = blockIdx.x;
    int dir = blk >> 6;
    int j0 = (blk & 63) * 6;

    const float* Whh = dir ? Whhb : Whhf;
    const float* bih = dir ? bihb : bihf;
    const float* bhh = dir ? bhhb : bhhf;

    for (int idx = tid; idx < 24 * HN; idx += REC_THREADS) {
        int r = idx / HN, k = idx % HN;
        int wrow = (r / 6) * HN + j0 + (r % 6);
        ws[r * HN + k] = Whh[(size_t)wrow * HN + k];
    }
    if (tid < 24) {
        int ng = (tid / 6) * HN + j0 + (tid % 6);
        bias_s[tid] = bih[ng] + bhh[ng];
    }
    if (tid < BN) sent_s[tid] = g_sent[tid];

    int be = tid / 6, je = tid % 6;
    g_h[((dir * 2 + 0) * BN + be) * HN + j0 + je] = h0[((size_t)dir * BN + be) * HN + j0 + je];
    float creg = c0[((size_t)dir * BN + be) * HN + j0 + je];

    int ks = tid / 96;
    int rem = tid % 96;
    int rg = rem >> 5;
    int bp = rem & 31;
    int kbase = ks * 96;
    int b0 = bp, b1 = bp + 32;

    grid_barrier();

    for (int s = 0; s < SN; s++) {
        int p = s & 1;
        int t = dir ? (SN - 1 - s) : s;

        // stage previous h into smem (coalesced)
        const float* hsrc = g_h + (size_t)(dir * 2 + p) * BN * HN;
        for (int idx = tid; idx < BN * 96; idx += REC_THREADS) {
            int b2 = idx / 96, q4 = (idx % 96) * 4;
            *(float4*)&hs[b2 * 388 + q4] = *(const float4*)&hsrc[b2 * HN + q4];
        }
        __syncthreads();

        // GEMV: 8 rows x 2 batches x 96 k per thread, packed f32x2
        {
            unsigned long long acc[8][2];
            #pragma unroll
            for (int i = 0; i < 8; i++) { acc[i][0] = 0ull; acc[i][1] = 0ull; }
            const float* hp0 = &hs[b0 * 388 + kbase];
            const float* hp1 = &hs[b1 * 388 + kbase];
            const float* wp  = &ws[(rg * 8) * HN + kbase];
            #pragma unroll 2
            for (int k = 0; k < 96; k += 4) {
                ulonglong2 h0v = *(const ulonglong2*)(hp0 + k);
                ulonglong2 h1v = *(const ulonglong2*)(hp1 + k);
                #pragma unroll
                for (int i = 0; i < 8; i++) {
                    ulonglong2 wv = *(const ulonglong2*)(wp + i * HN + k);
                    acc[i][0] = fma2(h0v.x, wv.x, acc[i][0]);
                    acc[i][0] = fma2(h0v.y, wv.y, acc[i][0]);
                    acc[i][1] = fma2(h1v.x, wv.x, acc[i][1]);
                    acc[i][1] = fma2(h1v.y, wv.y, acc[i][1]);
                }
            }
            #pragma unroll
            for (int i = 0; i < 8; i++) {
                int r = rg * 8 + i;
                P[(ks * 24 + r) * 65 + b0] = unpack_sum(acc[i][0]);
                P[(ks * 24 + r) * 65 + b1] = unpack_sum(acc[i][1]);
            }
        }
        __syncthreads();

        // cell update: thread (be, je) owns gates rows {je, 6+je, 12+je, 18+je}
        {
            bool valid = (t < sent_s[be]);
            const float* xgp = &g_xg[((size_t)(dir * SN + t) * BN + be) * GN];
            float g4[4];
            #pragma unroll
            for (int g = 0; g < 4; g++) {
                int r = g * 6 + je;
                float sum = P[(0 * 24 + r) * 65 + be] + P[(1 * 24 + r) * 65 + be]
                          + P[(2 * 24 + r) * 65 + be] + P[(3 * 24 + r) * 65 + be];
                float x = valid ? xgp[g * HN + j0 + je] : bias_s[r];
                g4[g] = sum + x;
            }
            float ig = 1.f / (1.f + expf(-g4[0]));
            float fg = 1.f / (1.f + expf(-g4[1]));
            float cg = tanhf(g4[2]);
            float og = 1.f / (1.f + expf(-g4[3]));
            creg = fg * creg + ig * cg;
            float hv = og * tanhf(creg);
            g_h[((dir * 2 + (p ^ 1)) * BN + be) * HN + j0 + je] = hv;
            g_lstm[((size_t)be * SN + t) * (2 * HN) + dir * HN + j0 + je] = hv;
        }
        grid_barrier();
    }
}

// ---------------- K4: output linear (Wlin cached in smem, 16 rows/block) -------
__global__ void __launch_bounds__(256) out_kernel(
    const float* __restrict__ Wlin, const float* __restrict__ blin,
    float* __restrict__ out)
{
    extern __shared__ float Wl[];   // 22*768 floats
    int tid = threadIdx.x;
    int lane = tid & 31, w = tid >> 5;
    for (int idx = tid; idx < TN * 768; idx += 256) Wl[idx] = Wlin[idx];
    __syncthreads();

    int base = blockIdx.x * 16;
    #pragma unroll
    for (int rr = 0; rr < 2; rr++) {
        int row = base + w * 2 + rr;
        const float* src = g_lstm + (size_t)row * 768;
        float rs[24];
        #pragma unroll
        for (int i = 0; i < 24; i++) rs[i] = src[lane + 32 * i];
        for (int o = 0; o < TN; o++) {
            const float* wr = &Wl[o * 768];
            float s = 0.f;
            #pragma unroll
            for (int i = 0; i < 24; i++) s += rs[i] * wr[lane + 32 * i];
            #pragma unroll
            for (int off = 16; off; off >>= 1) s += __shfl_down_sync(0xffffffffu, s, off);
            if (lane == 0) out[(size_t)row * TN + o] = s + blin[o];
        }
    }
}

// ---------------- launch --------------------------------------------------------
extern "C" void kernel_launch(void* const* d_in, const int* in_sizes, int n_in,
                              void* d_out, int out_size) {
    const float* hs   = (const float*)d_in[0];
    const float* h0   = (const float*)d_in[1];
    const float* c0   = (const float*)d_in[2];
    const float* Wihf = (const float*)d_in[3];
    const float* Whhf = (const float*)d_in[4];
    const float* bihf = (const float*)d_in[5];
    const float* bhhf = (const float*)d_in[6];
    const float* Wihb = (const float*)d_in[7];
    const float* Whhb = (const float*)d_in[8];
    const float* bihb = (const float*)d_in[9];
    const float* bhhb = (const float*)d_in[10];
    const float* Wlin = (const float*)d_in[11];
    const float* blin = (const float*)d_in[12];
    const void*  sid  = d_in[13];
    const void*  msk  = d_in[14];

    meta_kernel<<<BN, 256>>>(sid, msk);
    gather_kernel<<<dim3(SN, BN), 192>>>(hs, sid);
    proj_kernel<<<dim3(GN / 128, SN / 128, 2 * BN), 256>>>(Wihf, Wihb, bihf, bhhf, bihb, bhhb);

    const int rec_smem = (9216 + 24832 + 6240 + 24 + 64) * 4;
    cudaFuncSetAttribute(lstm_kernel, cudaFuncAttributeMaxDynamicSharedMemorySize, rec_smem);
    lstm_kernel<<<NBLK_REC, REC_THREADS, rec_smem>>>(Whhf, Whhb, bihf, bhhf, bihb, bhhb, h0, c0);

    const int out_smem = TN * 768 * 4;
    cudaFuncSetAttribute(out_kernel, cudaFuncAttributeMaxDynamicSharedMemorySize, out_smem);
    out_kernel<<<(BN * SN) / 16, 256, out_smem>>>(Wlin, blin, (float*)d_out);
}